// round 7
// baseline (speedup 1.0000x reference)
#include <cuda_runtime.h>
#include <cuda_fp16.h>
#include <math.h>
#include <stdint.h>

// Problem constants
#define BATCH   40
#define NSEQ    257
#define DMODEL  1024
#define FFDIM   4096
#define NHEAD   16
#define HDIM    64
#define TOK     (BATCH * NSEQ)      // 10280
#define QK_SCALE 0.125f

// ---------------- scratch ----------------
__device__ __half g_xln_h [TOK * DMODEL];
__device__ __half g_q_h   [TOK * DMODEL];
__device__ __half g_k_h   [TOK * DMODEL];
__device__ __half g_v_h   [TOK * DMODEL];
__device__ __half g_attn_h[TOK * DMODEL];
__device__ float  g_hidden[TOK * DMODEL];
__device__ __half g_h2_h  [TOK * DMODEL];
__device__ __half g_ff_h  [TOK * FFDIM];
__device__ __half g_wq_h  [DMODEL * DMODEL];
__device__ __half g_wk_h  [DMODEL * DMODEL];
__device__ __half g_wv_h  [DMODEL * DMODEL];
__device__ __half g_wo_h  [DMODEL * DMODEL];
__device__ __half g_fc1_h [FFDIM * DMODEL];
__device__ __half g_fc2_h [DMODEL * FFDIM];

// ---------------- helpers ----------------
__device__ __forceinline__ float warpSum(float v) {
    #pragma unroll
    for (int o = 16; o > 0; o >>= 1) v += __shfl_xor_sync(0xffffffffu, v, o);
    return v;
}
__device__ __forceinline__ void mma_f16(float* d, const uint32_t* a, const uint32_t* b) {
    asm volatile(
        "mma.sync.aligned.m16n8k16.row.col.f32.f16.f16.f32 "
        "{%0,%1,%2,%3}, {%4,%5,%6,%7}, {%8,%9}, {%0,%1,%2,%3};"
        : "+f"(d[0]), "+f"(d[1]), "+f"(d[2]), "+f"(d[3])
        : "r"(a[0]), "r"(a[1]), "r"(a[2]), "r"(a[3]), "r"(b[0]), "r"(b[1]));
}
__device__ __forceinline__ uint32_t smem_u32(const void* p) {
    return (uint32_t)__cvta_generic_to_shared(p);
}
__device__ __forceinline__ void ldsm_x4(uint32_t& r0, uint32_t& r1, uint32_t& r2,
                                        uint32_t& r3, uint32_t addr) {
    asm volatile("ldmatrix.sync.aligned.m8n8.x4.shared.b16 {%0,%1,%2,%3}, [%4];"
                 : "=r"(r0), "=r"(r1), "=r"(r2), "=r"(r3) : "r"(addr));
}
__device__ __forceinline__ void ldsm_x4_t(uint32_t& r0, uint32_t& r1, uint32_t& r2,
                                          uint32_t& r3, uint32_t addr) {
    asm volatile("ldmatrix.sync.aligned.m8n8.x4.trans.shared.b16 {%0,%1,%2,%3}, [%4];"
                 : "=r"(r0), "=r"(r1), "=r"(r2), "=r"(r3) : "r"(addr));
}
__device__ __forceinline__ uint32_t packh2(float a, float b) {
    __half2 h = __floats2half2_rn(a, b);
    return *(uint32_t*)&h;
}

// ---------------- weight conversion: fp32 -> fp16 ----------------
__global__ void cvt_half_kernel(const float4* __restrict__ in, uint2* __restrict__ out, int n4)
{
    int i = blockIdx.x * blockDim.x + threadIdx.x;
    if (i < n4) {
        float4 v = in[i];
        uint2 o;
        o.x = packh2(v.x, v.y);
        o.y = packh2(v.z, v.w);
        out[i] = o;
    }
}

// ---------------- LayerNorm -> half out ----------------
__global__ void ln_kernel(const float* __restrict__ x,
                          const float* __restrict__ w,
                          const float* __restrict__ b,
                          __half* __restrict__ y)
{
    int row = blockIdx.x;
    int tid = threadIdx.x;
    const float* xr = x + (size_t)row * DMODEL;
    float4 v = *(const float4*)&xr[tid * 4];

    float s  = v.x + v.y + v.z + v.w;
    float s2 = v.x * v.x + v.y * v.y + v.z * v.z + v.w * v.w;

    __shared__ float redS[8], redS2[8];
    int lane = tid & 31, wid = tid >> 5;
    s  = warpSum(s);
    s2 = warpSum(s2);
    if (lane == 0) { redS[wid] = s; redS2[wid] = s2; }
    __syncthreads();
    float ts = 0.f, ts2 = 0.f;
    #pragma unroll
    for (int i = 0; i < 8; i++) { ts += redS[i]; ts2 += redS2[i]; }
    float mean = ts * (1.0f / DMODEL);
    float var  = ts2 * (1.0f / DMODEL) - mean * mean;
    float r    = rsqrtf(var + 1e-5f);

    float4 wv = *(const float4*)&w[tid * 4];
    float4 bv = *(const float4*)&b[tid * 4];
    float o0 = (v.x - mean) * r * wv.x + bv.x;
    float o1 = (v.y - mean) * r * wv.y + bv.y;
    float o2 = (v.z - mean) * r * wv.z + bv.z;
    float o3 = (v.w - mean) * r * wv.w + bv.w;
    uint2 st;
    st.x = packh2(o0, o1);
    st.y = packh2(o2, o3);
    *(uint2*)&y[(size_t)row * DMODEL + tid * 4] = st;
}

// ---------------- fp16 tensor-core NT GEMM (ldmatrix, 128x256) ----------------
// C[M,N] = epilogue(A[M,K] @ B[N,K]^T + bias)
// MODE 0: (acc+bias)*alpha -> half   MODE 1: quick-gelu -> half   MODE 2: +res -> float
#define GBM 128
#define GBN 256
#define GBK 32      // halves per K-tile
#define PH  40      // smem pitch in halves (80B)
#define STG 4

template<int MODE>
__device__ __forceinline__ void gemm_body(
    const __half* __restrict__ A, const __half* __restrict__ B,
    const float* __restrict__ bias, const float* __restrict__ res,
    void* __restrict__ Cv, int M, int N, int K, float alpha, int bm, int bn)
{
    __shared__ __half As[STG][GBM][PH];
    __shared__ __half Bs[STG][GBN][PH];

    const int tid  = threadIdx.x;
    const int lane = tid & 31;
    const int wid  = tid >> 5;
    const int wm   = (wid & 1) * 64;    // 2 warps over M (64 rows each)
    const int wn   = (wid >> 1) * 64;   // 4 warps over N (64 cols each)

    float acc[4][8][4];
    #pragma unroll
    for (int i = 0; i < 4; i++)
        #pragma unroll
        for (int j = 0; j < 8; j++)
            #pragma unroll
            for (int q = 0; q < 4; q++) acc[i][j][q] = 0.f;

    const int ktiles = K / GBK;

    auto load_tile = [&](int kt, int s) {
        // A: 128 rows x 4 chunks of 16B
        #pragma unroll
        for (int i = 0; i < 2; i++) {
            int idx = tid + 256 * i;
            int row = idx >> 2, ch = idx & 3;
            uint32_t dst = smem_u32(&As[s][row][ch * 8]);
            const __half* src = A + (size_t)(bm + row) * K + kt * GBK + ch * 8;
            int sz = (bm + row < M) ? 16 : 0;
            asm volatile("cp.async.ca.shared.global [%0], [%1], 16, %2;"
                         :: "r"(dst), "l"(src), "r"(sz));
        }
        // B: 256 rows x 4 chunks of 16B
        #pragma unroll
        for (int i = 0; i < 4; i++) {
            int idx = tid + 256 * i;
            int row = idx >> 2, ch = idx & 3;
            uint32_t dst = smem_u32(&Bs[s][row][ch * 8]);
            const __half* src = B + (size_t)(bn + row) * K + kt * GBK + ch * 8;
            asm volatile("cp.async.ca.shared.global [%0], [%1], 16;"
                         :: "r"(dst), "l"(src));
        }
        asm volatile("cp.async.commit_group;");
    };

    const int l15 = lane & 15;
    const int lhi = lane >> 4;           // 0/1 -> k-half selector for ldmatrix

    auto compute_tile = [&](int s) {
        #pragma unroll
        for (int ks = 0; ks < 2; ks++) {
            const int kc = ks * 16 + lhi * 8;    // ldmatrix col (halves)
            uint32_t af[4][4];
            uint32_t bf[8][2];
            #pragma unroll
            for (int mt = 0; mt < 4; mt++) {
                uint32_t adr = smem_u32(&As[s][wm + mt * 16 + l15][kc]);
                ldsm_x4(af[mt][0], af[mt][1], af[mt][2], af[mt][3], adr);
            }
            #pragma unroll
            for (int g = 0; g < 4; g++) {
                uint32_t adr = smem_u32(&Bs[s][wn + g * 16 + l15][kc]);
                ldsm_x4(bf[2*g][0], bf[2*g+1][0], bf[2*g][1], bf[2*g+1][1], adr);
            }
            #pragma unroll
            for (int mt = 0; mt < 4; mt++)
                #pragma unroll
                for (int nt = 0; nt < 8; nt++)
                    mma_f16(acc[mt][nt], af[mt], bf[nt]);
        }
    };

    #pragma unroll
    for (int s = 0; s < STG - 1; s++)
        if (s < ktiles) load_tile(s, s);

    int cur = 0, pre = STG - 1;
    for (int kt = 0; kt < ktiles; kt++) {
        asm volatile("cp.async.wait_group %0;" :: "n"(STG - 2));
        __syncthreads();
        if (kt + STG - 1 < ktiles) load_tile(kt + STG - 1, pre);
        compute_tile(cur);
        cur = (cur + 1 == STG) ? 0 : cur + 1;
        pre = (pre + 1 == STG) ? 0 : pre + 1;
    }

    // epilogue
    #pragma unroll
    for (int mt = 0; mt < 4; mt++) {
        int row0 = bm + wm + mt * 16 + (lane >> 2);
        #pragma unroll
        for (int nt = 0; nt < 8; nt++) {
            int col = bn + wn + nt * 8 + (lane & 3) * 2;
            float b0 = bias[col], b1 = bias[col + 1];
            #pragma unroll
            for (int h = 0; h < 2; h++) {
                int row = row0 + h * 8;
                if (row >= M) continue;
                float v0 = acc[mt][nt][h * 2 + 0] + b0;
                float v1 = acc[mt][nt][h * 2 + 1] + b1;
                if (MODE == 0) {
                    v0 *= alpha; v1 *= alpha;
                    *(uint32_t*)&((__half*)Cv)[(size_t)row * N + col] = packh2(v0, v1);
                } else if (MODE == 1) {
                    v0 = v0 / (1.0f + expf(-1.702f * v0));
                    v1 = v1 / (1.0f + expf(-1.702f * v1));
                    *(uint32_t*)&((__half*)Cv)[(size_t)row * N + col] = packh2(v0, v1);
                } else {
                    const float* rr = &res[(size_t)row * N + col];
                    v0 += rr[0]; v1 += rr[1];
                    *(float2*)&((float*)Cv)[(size_t)row * N + col] = make_float2(v0, v1);
                }
            }
        }
    }
}

template<int MODE>
__global__ __launch_bounds__(256, 1)
void gemm_h(const __half* __restrict__ A, const __half* __restrict__ B,
            const float* __restrict__ bias, const float* __restrict__ res,
            void* __restrict__ C, int M, int N, int K, float alpha)
{
    gemm_body<MODE>(A, B, bias, res, C, M, N, K, alpha,
                    blockIdx.y * GBM, blockIdx.x * GBN);
}

__global__ __launch_bounds__(256, 1)
void gemm_qkv(const __half* __restrict__ A,
              const __half* __restrict__ wq, const __half* __restrict__ wk,
              const __half* __restrict__ wv,
              const float* __restrict__ bq, const float* __restrict__ bk,
              const float* __restrict__ bv,
              __half* __restrict__ q, __half* __restrict__ k, __half* __restrict__ v,
              int M, int K)
{
    const int which = blockIdx.x >> 2;          // DMODEL/GBN = 4 tiles each
    const int bn = (blockIdx.x & 3) * GBN;
    const __half* B   = (which == 0) ? wq : (which == 1) ? wk : wv;
    const float* bias = (which == 0) ? bq : (which == 1) ? bk : bv;
    __half* C         = (which == 0) ? q  : (which == 1) ? k  : v;
    const float alpha = (which == 0) ? QK_SCALE : 1.0f;
    gemm_body<0>(A, B, bias, nullptr, C, M, DMODEL, K, alpha,
                 blockIdx.y * GBM, bn);
}

// ---------------- fp16 tensor-core attention (ldmatrix) ----------------
#define AQT 64
#define AKT 64
#define NKT 5
#define QPH 72      // Q/KV tile pitch in halves (144B)
#define SPF 332     // fp32 score pitch
#define PPH 344     // half P pitch (688B)

#define OFF_QS   0
#define OFF_KVS  (AQT * QPH * 2)
#define OFF_SS   (OFF_KVS + AKT * QPH * 2)
#define OFF_PS   (OFF_SS + AQT * SPF * 4)
#define OFF_SINV (OFF_PS + AQT * PPH * 2)
#define ATT_SMEM (OFF_SINV + AQT * 4)

__global__ __launch_bounds__(256)
void attn_h(const __half* __restrict__ Q, const __half* __restrict__ K,
            const __half* __restrict__ V, __half* __restrict__ O)
{
    extern __shared__ __align__(16) char smraw[];
    __half (*Qs)[QPH]  = (__half(*)[QPH])(smraw + OFF_QS);
    __half (*KVs)[QPH] = (__half(*)[QPH])(smraw + OFF_KVS);
    float  (*Ss)[SPF]  = (float(*)[SPF]) (smraw + OFF_SS);
    __half (*Ps)[PPH]  = (__half(*)[PPH])(smraw + OFF_PS);
    float* sinv        = (float*)(smraw + OFF_SINV);

    const int qt  = blockIdx.x * AQT;
    const int bh  = blockIdx.y;
    const int b   = bh >> 4, h = bh & 15;
    const size_t base = (size_t)b * NSEQ * DMODEL + (size_t)h * HDIM;
    const int tid  = threadIdx.x;
    const int lane = tid & 31;
    const int wid  = tid >> 5;
    const int wm   = (wid & 3) * 16;
    const int wn   = (wid >> 2) * 32;
    const int l15  = lane & 15;
    const int lhi  = lane >> 4;

    // load Q tile [64 q][64 d]
    #pragma unroll
    for (int i = 0; i < 2; i++) {
        int idx = tid + 256 * i;
        int row = idx >> 3, ch = idx & 7;
        uint4 v = make_uint4(0u, 0u, 0u, 0u);
        if (qt + row < NSEQ)
            v = *(const uint4*)&Q[base + (size_t)(qt + row) * DMODEL + ch * 8];
        *(uint4*)&Qs[row][ch * 8] = v;
    }

    // ---- phase 1: S = Q K^T ----
    for (int t = 0; t < NKT; t++) {
        int kt0 = t * AKT;
        __syncthreads();
        #pragma unroll
        for (int i = 0; i < 2; i++) {
            int idx = tid + 256 * i;
            int row = idx >> 3, ch = idx & 7;
            uint4 v = make_uint4(0u, 0u, 0u, 0u);
            if (kt0 + row < NSEQ)
                v = *(const uint4*)&K[base + (size_t)(kt0 + row) * DMODEL + ch * 8];
            *(uint4*)&KVs[row][ch * 8] = v;
        }
        __syncthreads();

        float accS[4][4];
        #pragma unroll
        for (int nt = 0; nt < 4; nt++)
            #pragma unroll
            for (int q = 0; q < 4; q++) accS[nt][q] = 0.f;

        #pragma unroll
        for (int ks = 0; ks < 4; ks++) {
            const int kc = ks * 16 + lhi * 8;
            uint32_t af[4];
            ldsm_x4(af[0], af[1], af[2], af[3],
                    smem_u32(&Qs[wm + l15][kc]));
            uint32_t bf[4][2];
            #pragma unroll
            for (int g = 0; g < 2; g++) {
                ldsm_x4(bf[2*g][0], bf[2*g+1][0], bf[2*g][1], bf[2*g+1][1],
                        smem_u32(&KVs[wn + g * 16 + l15][kc]));
            }
            #pragma unroll
            for (int nt = 0; nt < 4; nt++)
                mma_f16(accS[nt], af, bf[nt]);
        }
        int row = wm + (lane >> 2);
        #pragma unroll
        for (int nt = 0; nt < 4; nt++) {
            int col = kt0 + wn + nt * 8 + (lane & 3) * 2;
            Ss[row    ][col    ] = accS[nt][0];
            Ss[row    ][col + 1] = accS[nt][1];
            Ss[row + 8][col    ] = accS[nt][2];
            Ss[row + 8][col + 1] = accS[nt][3];
        }
    }
    __syncthreads();

    // ---- softmax (4 threads per row), P -> half ----
    {
        int row = tid >> 2, r = tid & 3;
        float m = -1e30f;
        for (int k = r; k < NSEQ; k += 4) m = fmaxf(m, Ss[row][k]);
        m = fmaxf(m, __shfl_xor_sync(0xffffffffu, m, 1));
        m = fmaxf(m, __shfl_xor_sync(0xffffffffu, m, 2));
        float sum = 0.f;
        for (int k = r; k < NKT * AKT; k += 4) {
            if (k < NSEQ) {
                float e = __expf(Ss[row][k] - m);
                Ps[row][k] = __float2half_rn(e);
                sum += e;
            } else {
                Ps[row][k] = __float2half_rn(0.f);
            }
        }
        sum += __shfl_xor_sync(0xffffffffu, sum, 1);
        sum += __shfl_xor_sync(0xffffffffu, sum, 2);
        if (r == 0) sinv[row] = 1.0f / sum;
    }

    // ---- phase 2: O = P V ----
    float accO[4][4];
    #pragma unroll
    for (int nt = 0; nt < 4; nt++)
        #pragma unroll
        for (int q = 0; q < 4; q++) accO[nt][q] = 0.f;

    for (int t = 0; t < NKT; t++) {
        int kt0 = t * AKT;
        __syncthreads();
        // V tile row-major [seq][d] (no transpose; ldmatrix.trans below)
        #pragma unroll
        for (int i = 0; i < 2; i++) {
            int idx = tid + 256 * i;
            int row = idx >> 3, ch = idx & 7;
            uint4 v = make_uint4(0u, 0u, 0u, 0u);
            if (kt0 + row < NSEQ)
                v = *(const uint4*)&V[base + (size_t)(kt0 + row) * DMODEL + ch * 8];
            *(uint4*)&KVs[row][ch * 8] = v;
        }
        __syncthreads();

        #pragma unroll
        for (int ks = 0; ks < 4; ks++) {
            const int kc = ks * 16 + lhi * 8;
            uint32_t af[4];
            ldsm_x4(af[0], af[1], af[2], af[3],
                    smem_u32(&Ps[wm + l15][kt0 + kc]));
            // V as col-major B via ldmatrix.trans: seq row = ks*16+(l&15), d col = wn+g*16+(l>>4)*8
            uint32_t bf[4][2];
            #pragma unroll
            for (int g = 0; g < 2; g++) {
                ldsm_x4_t(bf[2*g][0], bf[2*g][1], bf[2*g+1][0], bf[2*g+1][1],
                          smem_u32(&KVs[ks * 16 + l15][wn + g * 16 + lhi * 8]));
            }
            #pragma unroll
            for (int nt = 0; nt < 4; nt++)
                mma_f16(accO[nt], af, bf[nt]);
        }
    }

    // epilogue
    {
        int row = wm + (lane >> 2);
        float i0 = sinv[row], i1 = sinv[row + 8];
        #pragma unroll
        for (int nt = 0; nt < 4; nt++) {
            int col = wn + nt * 8 + (lane & 3) * 2;
            if (qt + row < NSEQ)
                *(uint32_t*)&O[base + (size_t)(qt + row) * DMODEL + col] =
                    packh2(accO[nt][0] * i0, accO[nt][1] * i0);
            if (qt + row + 8 < NSEQ)
                *(uint32_t*)&O[base + (size_t)(qt + row + 8) * DMODEL + col] =
                    packh2(accO[nt][2] * i1, accO[nt][3] * i1);
        }
    }
}

// ---------------- launch ----------------
extern "C" void kernel_launch(void* const* d_in, const int* in_sizes, int n_in,
                              void* d_out, int out_size)
{
    const float* hs     = (const float*)d_in[0];
    const float* ln1_w  = (const float*)d_in[1];
    const float* ln1_b  = (const float*)d_in[2];
    const float* wq     = (const float*)d_in[3];
    const float* bq     = (const float*)d_in[4];
    const float* wk     = (const float*)d_in[5];
    const float* bk     = (const float*)d_in[6];
    const float* wv     = (const float*)d_in[7];
    const float* bv     = (const float*)d_in[8];
    const float* wo     = (const float*)d_in[9];
    const float* bo     = (const float*)d_in[10];
    const float* ln2_w  = (const float*)d_in[11];
    const float* ln2_b  = (const float*)d_in[12];
    const float* fc1_w  = (const float*)d_in[13];
    const float* fc1_b  = (const float*)d_in[14];
    const float* fc2_w  = (const float*)d_in[15];
    const float* fc2_b  = (const float*)d_in[16];
    float* out          = (float*)d_out;

    static __half *xln=nullptr,*q=nullptr,*k=nullptr,*v=nullptr,*attn=nullptr,
                  *h2=nullptr,*ff=nullptr,
                  *wqh=nullptr,*wkh=nullptr,*wvh=nullptr,*woh=nullptr,
                  *fc1h=nullptr,*fc2h=nullptr;
    static float *hidden=nullptr;
    if (!xln) {
        cudaGetSymbolAddress((void**)&xln,    g_xln_h);
        cudaGetSymbolAddress((void**)&q,      g_q_h);
        cudaGetSymbolAddress((void**)&k,      g_k_h);
        cudaGetSymbolAddress((void**)&v,      g_v_h);
        cudaGetSymbolAddress((void**)&attn,   g_attn_h);
        cudaGetSymbolAddress((void**)&hidden, g_hidden);
        cudaGetSymbolAddress((void**)&h2,     g_h2_h);
        cudaGetSymbolAddress((void**)&ff,     g_ff_h);
        cudaGetSymbolAddress((void**)&wqh,    g_wq_h);
        cudaGetSymbolAddress((void**)&wkh,    g_wk_h);
        cudaGetSymbolAddress((void**)&wvh,    g_wv_h);
        cudaGetSymbolAddress((void**)&woh,    g_wo_h);
        cudaGetSymbolAddress((void**)&fc1h,   g_fc1_h);
        cudaGetSymbolAddress((void**)&fc2h,   g_fc2_h);
        cudaFuncSetAttribute(attn_h, cudaFuncAttributeMaxDynamicSharedMemorySize, ATT_SMEM);
    }

    const int mtiles = (TOK + GBM - 1) / GBM;   // 81
    const int n4w = DMODEL * DMODEL / 4;
    const int n4f = FFDIM * DMODEL / 4;

    // 0) convert weights to half
    cvt_half_kernel<<<n4w / 256, 256>>>((const float4*)wq,    (uint2*)wqh,  n4w);
    cvt_half_kernel<<<n4w / 256, 256>>>((const float4*)wk,    (uint2*)wkh,  n4w);
    cvt_half_kernel<<<n4w / 256, 256>>>((const float4*)wv,    (uint2*)wvh,  n4w);
    cvt_half_kernel<<<n4w / 256, 256>>>((const float4*)wo,    (uint2*)woh,  n4w);
    cvt_half_kernel<<<n4f / 256, 256>>>((const float4*)fc1_w, (uint2*)fc1h, n4f);
    cvt_half_kernel<<<n4f / 256, 256>>>((const float4*)fc2_w, (uint2*)fc2h, n4f);

    // 1) LN1 -> half
    ln_kernel<<<TOK, 256>>>(hs, ln1_w, ln1_b, xln);

    // 2) fused QKV projections
    gemm_qkv<<<dim3(12, mtiles), 256>>>(xln, wqh, wkh, wvh, bq, bk, bv,
                                        q, k, v, TOK, DMODEL);

    // 3) attention
    attn_h<<<dim3((NSEQ + AQT - 1)/AQT, BATCH*NHEAD), 256, ATT_SMEM>>>(q, k, v, attn);

    // 4) O projection + residual -> fp32 hidden
    gemm_h<2><<<dim3(DMODEL/GBN, mtiles), 256>>>(attn, woh, bo, hs, hidden,
                                                 TOK, DMODEL, DMODEL, 1.0f);

    // 5) LN2 -> half
    ln_kernel<<<TOK, 256>>>(hidden, ln2_w, ln2_b, h2);

    // 6) FC1 + quick-gelu -> half
    gemm_h<1><<<dim3(FFDIM/GBN, mtiles), 256>>>(h2, fc1h, fc1_b, nullptr, ff,
                                                TOK, FFDIM, DMODEL, 1.0f);

    // 7) FC2 + residual -> fp32 output
    gemm_h<2><<<dim3(DMODEL/GBN, mtiles), 256>>>(ff, fc2h, fc2_b, hidden, out,
                                                 TOK, DMODEL, FFDIM, 1.0f);
}

// round 8
// speedup vs baseline: 1.1193x; 1.1193x over previous
#include <cuda_runtime.h>
#include <cuda_fp16.h>
#include <math.h>
#include <stdint.h>

// Problem constants
#define BATCH   40
#define NSEQ    257
#define DMODEL  1024
#define FFDIM   4096
#define NHEAD   16
#define HDIM    64
#define TOK     (BATCH * NSEQ)      // 10280
#define QK_SCALE 0.125f

// ---------------- scratch ----------------
__device__ __half g_xln_h [TOK * DMODEL];
__device__ __half g_q_h   [TOK * DMODEL];
__device__ __half g_k_h   [TOK * DMODEL];
__device__ __half g_v_h   [TOK * DMODEL];
__device__ __half g_attn_h[TOK * DMODEL];
__device__ float  g_hidden[TOK * DMODEL];
__device__ __half g_h2_h  [TOK * DMODEL];
__device__ __half g_ff_h  [TOK * FFDIM];
__device__ __half g_wq_h  [DMODEL * DMODEL];
__device__ __half g_wk_h  [DMODEL * DMODEL];
__device__ __half g_wv_h  [DMODEL * DMODEL];
__device__ __half g_wo_h  [DMODEL * DMODEL];
__device__ __half g_fc1_h [FFDIM * DMODEL];
__device__ __half g_fc2_h [DMODEL * FFDIM];

// ---------------- helpers ----------------
__device__ __forceinline__ float warpSum(float v) {
    #pragma unroll
    for (int o = 16; o > 0; o >>= 1) v += __shfl_xor_sync(0xffffffffu, v, o);
    return v;
}
__device__ __forceinline__ void mma_f16(float* d, const uint32_t* a, const uint32_t* b) {
    asm volatile(
        "mma.sync.aligned.m16n8k16.row.col.f32.f16.f16.f32 "
        "{%0,%1,%2,%3}, {%4,%5,%6,%7}, {%8,%9}, {%0,%1,%2,%3};"
        : "+f"(d[0]), "+f"(d[1]), "+f"(d[2]), "+f"(d[3])
        : "r"(a[0]), "r"(a[1]), "r"(a[2]), "r"(a[3]), "r"(b[0]), "r"(b[1]));
}
__device__ __forceinline__ uint32_t smem_u32(const void* p) {
    return (uint32_t)__cvta_generic_to_shared(p);
}
__device__ __forceinline__ void ldsm_x4(uint32_t& r0, uint32_t& r1, uint32_t& r2,
                                        uint32_t& r3, uint32_t addr) {
    asm volatile("ldmatrix.sync.aligned.m8n8.x4.shared.b16 {%0,%1,%2,%3}, [%4];"
                 : "=r"(r0), "=r"(r1), "=r"(r2), "=r"(r3) : "r"(addr));
}
__device__ __forceinline__ void ldsm_x4_t(uint32_t& r0, uint32_t& r1, uint32_t& r2,
                                          uint32_t& r3, uint32_t addr) {
    asm volatile("ldmatrix.sync.aligned.m8n8.x4.trans.shared.b16 {%0,%1,%2,%3}, [%4];"
                 : "=r"(r0), "=r"(r1), "=r"(r2), "=r"(r3) : "r"(addr));
}
__device__ __forceinline__ uint32_t packh2(float a, float b) {
    __half2 h = __floats2half2_rn(a, b);
    return *(uint32_t*)&h;
}

// ---------------- weight conversion: fp32 -> fp16 ----------------
__global__ void cvt_half_kernel(const float4* __restrict__ in, uint2* __restrict__ out, int n4)
{
    int i = blockIdx.x * blockDim.x + threadIdx.x;
    if (i < n4) {
        float4 v = in[i];
        uint2 o;
        o.x = packh2(v.x, v.y);
        o.y = packh2(v.z, v.w);
        out[i] = o;
    }
}

// ---------------- LayerNorm -> half out ----------------
__global__ void ln_kernel(const float* __restrict__ x,
                          const float* __restrict__ w,
                          const float* __restrict__ b,
                          __half* __restrict__ y)
{
    int row = blockIdx.x;
    int tid = threadIdx.x;
    const float* xr = x + (size_t)row * DMODEL;
    float4 v = *(const float4*)&xr[tid * 4];

    float s  = v.x + v.y + v.z + v.w;
    float s2 = v.x * v.x + v.y * v.y + v.z * v.z + v.w * v.w;

    __shared__ float redS[8], redS2[8];
    int lane = tid & 31, wid = tid >> 5;
    s  = warpSum(s);
    s2 = warpSum(s2);
    if (lane == 0) { redS[wid] = s; redS2[wid] = s2; }
    __syncthreads();
    float ts = 0.f, ts2 = 0.f;
    #pragma unroll
    for (int i = 0; i < 8; i++) { ts += redS[i]; ts2 += redS2[i]; }
    float mean = ts * (1.0f / DMODEL);
    float var  = ts2 * (1.0f / DMODEL) - mean * mean;
    float r    = rsqrtf(var + 1e-5f);

    float4 wv = *(const float4*)&w[tid * 4];
    float4 bv = *(const float4*)&b[tid * 4];
    float o0 = (v.x - mean) * r * wv.x + bv.x;
    float o1 = (v.y - mean) * r * wv.y + bv.y;
    float o2 = (v.z - mean) * r * wv.z + bv.z;
    float o3 = (v.w - mean) * r * wv.w + bv.w;
    uint2 st;
    st.x = packh2(o0, o1);
    st.y = packh2(o2, o3);
    *(uint2*)&y[(size_t)row * DMODEL + tid * 4] = st;
}

// ---------------- fp16 tensor-core NT GEMM (512 threads, 128x256) ----------------
// C[M,N] = epilogue(A[M,K] @ B[N,K]^T + bias)
// MODE 0: (acc+bias)*alpha -> half   MODE 1: quick-gelu -> half   MODE 2: +res -> float
#define GBM 128
#define GBN 256
#define GBK 32      // halves per K-tile
#define PH  40      // smem pitch in halves (80B)
#define STG 4
#define GTHREADS 512

template<int MODE>
__device__ __forceinline__ void gemm_body(
    const __half* __restrict__ A, const __half* __restrict__ B,
    const float* __restrict__ bias, const float* __restrict__ res,
    void* __restrict__ Cv, int M, int N, int K, float alpha, int bm, int bn)
{
    __shared__ __half As[STG][GBM][PH];
    __shared__ __half Bs[STG][GBN][PH];

    const int tid  = threadIdx.x;
    const int lane = tid & 31;
    const int wid  = tid >> 5;          // 0..15
    const int wm   = (wid & 3) * 32;    // 4 warps over M (32 rows each)
    const int wn   = (wid >> 2) * 64;   // 4 warps over N (64 cols each)

    float acc[2][8][4];
    #pragma unroll
    for (int i = 0; i < 2; i++)
        #pragma unroll
        for (int j = 0; j < 8; j++)
            #pragma unroll
            for (int q = 0; q < 4; q++) acc[i][j][q] = 0.f;

    const int ktiles = K / GBK;

    auto load_tile = [&](int kt, int s) {
        // A: 128 rows x 4 chunks of 16B = 512 -> 1 per thread
        {
            int row = tid >> 2, ch = tid & 3;
            uint32_t dst = smem_u32(&As[s][row][ch * 8]);
            const __half* src = A + (size_t)(bm + row) * K + kt * GBK + ch * 8;
            int sz = (bm + row < M) ? 16 : 0;
            asm volatile("cp.async.ca.shared.global [%0], [%1], 16, %2;"
                         :: "r"(dst), "l"(src), "r"(sz));
        }
        // B: 256 rows x 4 chunks = 1024 -> 2 per thread
        #pragma unroll
        for (int i = 0; i < 2; i++) {
            int idx = tid + GTHREADS * i;
            int row = idx >> 2, ch = idx & 3;
            uint32_t dst = smem_u32(&Bs[s][row][ch * 8]);
            const __half* src = B + (size_t)(bn + row) * K + kt * GBK + ch * 8;
            asm volatile("cp.async.ca.shared.global [%0], [%1], 16;"
                         :: "r"(dst), "l"(src));
        }
        asm volatile("cp.async.commit_group;");
    };

    const int l15 = lane & 15;
    const int lhi = lane >> 4;

    auto compute_tile = [&](int s) {
        #pragma unroll
        for (int ks = 0; ks < 2; ks++) {
            const int kc = ks * 16 + lhi * 8;
            uint32_t af[2][4];
            uint32_t bf[8][2];
            #pragma unroll
            for (int mt = 0; mt < 2; mt++) {
                uint32_t adr = smem_u32(&As[s][wm + mt * 16 + l15][kc]);
                ldsm_x4(af[mt][0], af[mt][1], af[mt][2], af[mt][3], adr);
            }
            #pragma unroll
            for (int g = 0; g < 4; g++) {
                uint32_t adr = smem_u32(&Bs[s][wn + g * 16 + l15][kc]);
                ldsm_x4(bf[2*g][0], bf[2*g+1][0], bf[2*g][1], bf[2*g+1][1], adr);
            }
            #pragma unroll
            for (int mt = 0; mt < 2; mt++)
                #pragma unroll
                for (int nt = 0; nt < 8; nt++)
                    mma_f16(acc[mt][nt], af[mt], bf[nt]);
        }
    };

    #pragma unroll
    for (int s = 0; s < STG - 1; s++)
        if (s < ktiles) load_tile(s, s);

    int cur = 0, pre = STG - 1;
    for (int kt = 0; kt < ktiles; kt++) {
        asm volatile("cp.async.wait_group %0;" :: "n"(STG - 2));
        __syncthreads();
        if (kt + STG - 1 < ktiles) load_tile(kt + STG - 1, pre);
        compute_tile(cur);
        cur = (cur + 1 == STG) ? 0 : cur + 1;
        pre = (pre + 1 == STG) ? 0 : pre + 1;
    }

    // epilogue
    #pragma unroll
    for (int mt = 0; mt < 2; mt++) {
        int row0 = bm + wm + mt * 16 + (lane >> 2);
        #pragma unroll
        for (int nt = 0; nt < 8; nt++) {
            int col = bn + wn + nt * 8 + (lane & 3) * 2;
            float b0 = bias[col], b1 = bias[col + 1];
            #pragma unroll
            for (int h = 0; h < 2; h++) {
                int row = row0 + h * 8;
                if (row >= M) continue;
                float v0 = acc[mt][nt][h * 2 + 0] + b0;
                float v1 = acc[mt][nt][h * 2 + 1] + b1;
                if (MODE == 0) {
                    v0 *= alpha; v1 *= alpha;
                    *(uint32_t*)&((__half*)Cv)[(size_t)row * N + col] = packh2(v0, v1);
                } else if (MODE == 1) {
                    v0 = v0 / (1.0f + expf(-1.702f * v0));
                    v1 = v1 / (1.0f + expf(-1.702f * v1));
                    *(uint32_t*)&((__half*)Cv)[(size_t)row * N + col] = packh2(v0, v1);
                } else {
                    const float* rr = &res[(size_t)row * N + col];
                    v0 += rr[0]; v1 += rr[1];
                    *(float2*)&((float*)Cv)[(size_t)row * N + col] = make_float2(v0, v1);
                }
            }
        }
    }
}

template<int MODE>
__global__ __launch_bounds__(GTHREADS, 1)
void gemm_h(const __half* __restrict__ A, const __half* __restrict__ B,
            const float* __restrict__ bias, const float* __restrict__ res,
            void* __restrict__ C, int M, int N, int K, float alpha)
{
    gemm_body<MODE>(A, B, bias, res, C, M, N, K, alpha,
                    blockIdx.y * GBM, blockIdx.x * GBN);
}

__global__ __launch_bounds__(GTHREADS, 1)
void gemm_qkv(const __half* __restrict__ A,
              const __half* __restrict__ wq, const __half* __restrict__ wk,
              const __half* __restrict__ wv,
              const float* __restrict__ bq, const float* __restrict__ bk,
              const float* __restrict__ bv,
              __half* __restrict__ q, __half* __restrict__ k, __half* __restrict__ v,
              int M, int K)
{
    const int which = blockIdx.x >> 2;
    const int bn = (blockIdx.x & 3) * GBN;
    const __half* B   = (which == 0) ? wq : (which == 1) ? wk : wv;
    const float* bias = (which == 0) ? bq : (which == 1) ? bk : bv;
    __half* C         = (which == 0) ? q  : (which == 1) ? k  : v;
    const float alpha = (which == 0) ? QK_SCALE : 1.0f;
    gemm_body<0>(A, B, bias, nullptr, C, M, DMODEL, K, alpha,
                 blockIdx.y * GBM, bn);
}

// ---------------- flash attention (fp16 mma, online softmax) ----------------
// qtile=128, 8 warps; warp w owns q rows w*16..w*16+15 across full width.
#define FQT 128
#define FKT 64
#define FNT 5           // ceil(257/64)
#define FPH 72          // smem pitch in halves (144B)

__global__ __launch_bounds__(256)
void fattn(const __half* __restrict__ Q, const __half* __restrict__ K,
           const __half* __restrict__ V, __half* __restrict__ O)
{
    __shared__ __half Qs[FQT][FPH];
    __shared__ __half Ks[FKT][FPH];
    __shared__ __half Vs[FKT][FPH];

    const int qt  = blockIdx.x * FQT;
    const int bh  = blockIdx.y;
    const int b   = bh >> 4, h = bh & 15;
    const size_t base = (size_t)b * NSEQ * DMODEL + (size_t)h * HDIM;
    const int tid  = threadIdx.x;
    const int lane = tid & 31;
    const int wid  = tid >> 5;
    const int qr0  = wid * 16;
    const int l15  = lane & 15;
    const int lhi  = lane >> 4;

    // load Q tile [128 q][64 d]: 128*8 chunks / 256 thr = 4 each
    #pragma unroll
    for (int i = 0; i < 4; i++) {
        int idx = tid + 256 * i;
        int row = idx >> 3, ch = idx & 7;
        uint4 v = make_uint4(0u, 0u, 0u, 0u);
        if (qt + row < NSEQ)
            v = *(const uint4*)&Q[base + (size_t)(qt + row) * DMODEL + ch * 8];
        *(uint4*)&Qs[row][ch * 8] = v;
    }
    __syncthreads();

    // preload Q fragments (K=64 -> 4 k-steps)
    uint32_t afq[4][4];
    #pragma unroll
    for (int ks = 0; ks < 4; ks++)
        ldsm_x4(afq[ks][0], afq[ks][1], afq[ks][2], afq[ks][3],
                smem_u32(&Qs[qr0 + l15][ks * 16 + lhi * 8]));

    float m0 = -1e30f, m1 = -1e30f, l0 = 0.f, l1 = 0.f;
    float accO[8][4];
    #pragma unroll
    for (int nt = 0; nt < 8; nt++)
        #pragma unroll
        for (int q = 0; q < 4; q++) accO[nt][q] = 0.f;

    for (int t = 0; t < FNT; t++) {
        const int kt0 = t * FKT;
        __syncthreads();
        // load K and V tiles: 64*8 chunks each = 512 -> 2 per thread each
        #pragma unroll
        for (int i = 0; i < 2; i++) {
            int idx = tid + 256 * i;
            int row = idx >> 3, ch = idx & 7;
            uint4 kv = make_uint4(0u, 0u, 0u, 0u);
            uint4 vv = make_uint4(0u, 0u, 0u, 0u);
            if (kt0 + row < NSEQ) {
                kv = *(const uint4*)&K[base + (size_t)(kt0 + row) * DMODEL + ch * 8];
                vv = *(const uint4*)&V[base + (size_t)(kt0 + row) * DMODEL + ch * 8];
            }
            *(uint4*)&Ks[row][ch * 8] = kv;
            *(uint4*)&Vs[row][ch * 8] = vv;
        }
        __syncthreads();

        // ---- S = Q K^T (16 x 64) ----
        float accS[8][4];
        #pragma unroll
        for (int nt = 0; nt < 8; nt++)
            #pragma unroll
            for (int q = 0; q < 4; q++) accS[nt][q] = 0.f;

        #pragma unroll
        for (int ks = 0; ks < 4; ks++) {
            const int kc = ks * 16 + lhi * 8;
            uint32_t bf[8][2];
            #pragma unroll
            for (int g = 0; g < 4; g++)
                ldsm_x4(bf[2*g][0], bf[2*g+1][0], bf[2*g][1], bf[2*g+1][1],
                        smem_u32(&Ks[g * 16 + l15][kc]));
            #pragma unroll
            for (int nt = 0; nt < 8; nt++)
                mma_f16(accS[nt], afq[ks], bf[nt]);
        }

        // ---- mask + row max (rows r and r+8; 4 threads per row) ----
        const int cbase = kt0 + (lane & 3) * 2;
        float tm0 = -1e30f, tm1 = -1e30f;
        #pragma unroll
        for (int nt = 0; nt < 8; nt++) {
            int c0 = cbase + nt * 8;
            if (c0 >= NSEQ)     { accS[nt][0] = -1e30f; accS[nt][2] = -1e30f; }
            if (c0 + 1 >= NSEQ) { accS[nt][1] = -1e30f; accS[nt][3] = -1e30f; }
            tm0 = fmaxf(tm0, fmaxf(accS[nt][0], accS[nt][1]));
            tm1 = fmaxf(tm1, fmaxf(accS[nt][2], accS[nt][3]));
        }
        tm0 = fmaxf(tm0, __shfl_xor_sync(0xffffffffu, tm0, 1));
        tm0 = fmaxf(tm0, __shfl_xor_sync(0xffffffffu, tm0, 2));
        tm1 = fmaxf(tm1, __shfl_xor_sync(0xffffffffu, tm1, 1));
        tm1 = fmaxf(tm1, __shfl_xor_sync(0xffffffffu, tm1, 2));

        float mn0 = fmaxf(m0, tm0), mn1 = fmaxf(m1, tm1);
        float sc0 = __expf(m0 - mn0), sc1 = __expf(m1 - mn1);
        m0 = mn0; m1 = mn1;

        // ---- P = exp(S - m); pack A-fragments for PV directly from regs ----
        uint32_t pf[4][4];
        float s0 = 0.f, s1 = 0.f;
        #pragma unroll
        for (int j = 0; j < 4; j++) {
            #pragma unroll
            for (int e = 0; e < 2; e++) {
                int nt = 2 * j + e;
                float p0 = __expf(accS[nt][0] - m0);
                float p1 = __expf(accS[nt][1] - m0);
                float p2 = __expf(accS[nt][2] - m1);
                float p3 = __expf(accS[nt][3] - m1);
                s0 += p0 + p1; s1 += p2 + p3;
                pf[j][0 + 2*e] = packh2(p0, p1);
                pf[j][1 + 2*e] = packh2(p2, p3);
            }
        }
        s0 += __shfl_xor_sync(0xffffffffu, s0, 1);
        s0 += __shfl_xor_sync(0xffffffffu, s0, 2);
        s1 += __shfl_xor_sync(0xffffffffu, s1, 1);
        s1 += __shfl_xor_sync(0xffffffffu, s1, 2);
        l0 = l0 * sc0 + s0;
        l1 = l1 * sc1 + s1;

        #pragma unroll
        for (int nt = 0; nt < 8; nt++) {
            accO[nt][0] *= sc0; accO[nt][1] *= sc0;
            accO[nt][2] *= sc1; accO[nt][3] *= sc1;
        }

        // ---- O += P V ----
        #pragma unroll
        for (int j = 0; j < 4; j++) {
            uint32_t bv[8][2];
            #pragma unroll
            for (int g = 0; g < 4; g++)
                ldsm_x4_t(bv[2*g][0], bv[2*g][1], bv[2*g+1][0], bv[2*g+1][1],
                          smem_u32(&Vs[j * 16 + l15][g * 16 + lhi * 8]));
            #pragma unroll
            for (int nt = 0; nt < 8; nt++)
                mma_f16(accO[nt], pf[j], bv[nt]);
        }
    }

    // ---- epilogue: O / l ----
    {
        int r = lane >> 2;
        int row0 = qt + qr0 + r;
        int row1 = row0 + 8;
        float i0 = 1.0f / l0, i1 = 1.0f / l1;
        #pragma unroll
        for (int nt = 0; nt < 8; nt++) {
            int col = nt * 8 + (lane & 3) * 2;
            if (row0 < NSEQ)
                *(uint32_t*)&O[base + (size_t)row0 * DMODEL + col] =
                    packh2(accO[nt][0] * i0, accO[nt][1] * i0);
            if (row1 < NSEQ)
                *(uint32_t*)&O[base + (size_t)row1 * DMODEL + col] =
                    packh2(accO[nt][2] * i1, accO[nt][3] * i1);
        }
    }
}

// ---------------- launch ----------------
extern "C" void kernel_launch(void* const* d_in, const int* in_sizes, int n_in,
                              void* d_out, int out_size)
{
    const float* hs     = (const float*)d_in[0];
    const float* ln1_w  = (const float*)d_in[1];
    const float* ln1_b  = (const float*)d_in[2];
    const float* wq     = (const float*)d_in[3];
    const float* bq     = (const float*)d_in[4];
    const float* wk     = (const float*)d_in[5];
    const float* bk     = (const float*)d_in[6];
    const float* wv     = (const float*)d_in[7];
    const float* bv     = (const float*)d_in[8];
    const float* wo     = (const float*)d_in[9];
    const float* bo     = (const float*)d_in[10];
    const float* ln2_w  = (const float*)d_in[11];
    const float* ln2_b  = (const float*)d_in[12];
    const float* fc1_w  = (const float*)d_in[13];
    const float* fc1_b  = (const float*)d_in[14];
    const float* fc2_w  = (const float*)d_in[15];
    const float* fc2_b  = (const float*)d_in[16];
    float* out          = (float*)d_out;

    static __half *xln=nullptr,*q=nullptr,*k=nullptr,*v=nullptr,*attn=nullptr,
                  *h2=nullptr,*ff=nullptr,
                  *wqh=nullptr,*wkh=nullptr,*wvh=nullptr,*woh=nullptr,
                  *fc1h=nullptr,*fc2h=nullptr;
    static float *hidden=nullptr;
    if (!xln) {
        cudaGetSymbolAddress((void**)&xln,    g_xln_h);
        cudaGetSymbolAddress((void**)&q,      g_q_h);
        cudaGetSymbolAddress((void**)&k,      g_k_h);
        cudaGetSymbolAddress((void**)&v,      g_v_h);
        cudaGetSymbolAddress((void**)&attn,   g_attn_h);
        cudaGetSymbolAddress((void**)&hidden, g_hidden);
        cudaGetSymbolAddress((void**)&h2,     g_h2_h);
        cudaGetSymbolAddress((void**)&ff,     g_ff_h);
        cudaGetSymbolAddress((void**)&wqh,    g_wq_h);
        cudaGetSymbolAddress((void**)&wkh,    g_wk_h);
        cudaGetSymbolAddress((void**)&wvh,    g_wv_h);
        cudaGetSymbolAddress((void**)&woh,    g_wo_h);
        cudaGetSymbolAddress((void**)&fc1h,   g_fc1_h);
        cudaGetSymbolAddress((void**)&fc2h,   g_fc2_h);
    }

    const int mtiles = (TOK + GBM - 1) / GBM;   // 81
    const int n4w = DMODEL * DMODEL / 4;
    const int n4f = FFDIM * DMODEL / 4;

    // 0) convert weights to half
    cvt_half_kernel<<<n4w / 256, 256>>>((const float4*)wq,    (uint2*)wqh,  n4w);
    cvt_half_kernel<<<n4w / 256, 256>>>((const float4*)wk,    (uint2*)wkh,  n4w);
    cvt_half_kernel<<<n4w / 256, 256>>>((const float4*)wv,    (uint2*)wvh,  n4w);
    cvt_half_kernel<<<n4w / 256, 256>>>((const float4*)wo,    (uint2*)woh,  n4w);
    cvt_half_kernel<<<n4f / 256, 256>>>((const float4*)fc1_w, (uint2*)fc1h, n4f);
    cvt_half_kernel<<<n4f / 256, 256>>>((const float4*)fc2_w, (uint2*)fc2h, n4f);

    // 1) LN1 -> half
    ln_kernel<<<TOK, 256>>>(hs, ln1_w, ln1_b, xln);

    // 2) fused QKV projections
    gemm_qkv<<<dim3(12, mtiles), GTHREADS>>>(xln, wqh, wkh, wvh, bq, bk, bv,
                                             q, k, v, TOK, DMODEL);

    // 3) flash attention
    fattn<<<dim3((NSEQ + FQT - 1) / FQT, BATCH * NHEAD), 256>>>(q, k, v, attn);

    // 4) O projection + residual -> fp32 hidden
    gemm_h<2><<<dim3(DMODEL/GBN, mtiles), GTHREADS>>>(attn, woh, bo, hs, hidden,
                                                      TOK, DMODEL, DMODEL, 1.0f);

    // 5) LN2 -> half
    ln_kernel<<<TOK, 256>>>(hidden, ln2_w, ln2_b, h2);

    // 6) FC1 + quick-gelu -> half
    gemm_h<1><<<dim3(FFDIM/GBN, mtiles), GTHREADS>>>(h2, fc1h, fc1_b, nullptr, ff,
                                                     TOK, FFDIM, DMODEL, 1.0f);

    // 7) FC2 + residual -> fp32 output
    gemm_h<2><<<dim3(DMODEL/GBN, mtiles), GTHREADS>>>(ff, fc2h, fc2_b, hidden, out,
                                                      TOK, DMODEL, FFDIM, 1.0f);
}

// round 9
// speedup vs baseline: 1.1212x; 1.0017x over previous
#include <cuda_runtime.h>
#include <cuda_fp16.h>
#include <math.h>
#include <stdint.h>

// Problem constants
#define BATCH   40
#define NSEQ    257
#define DMODEL  1024
#define FFDIM   4096
#define NHEAD   16
#define HDIM    64
#define TOK     (BATCH * NSEQ)      // 10280
#define QK_SCALE 0.125f

// ---------------- scratch ----------------
__device__ __half g_xln_h [TOK * DMODEL];
__device__ __half g_q_h   [TOK * DMODEL];
__device__ __half g_k_h   [TOK * DMODEL];
__device__ __half g_v_h   [TOK * DMODEL];
__device__ __half g_attn_h[TOK * DMODEL];
__device__ float  g_hidden[TOK * DMODEL];
__device__ __half g_h2_h  [TOK * DMODEL];
__device__ __half g_ff_h  [TOK * FFDIM];
__device__ __half g_wq_h  [DMODEL * DMODEL];
__device__ __half g_wk_h  [DMODEL * DMODEL];
__device__ __half g_wv_h  [DMODEL * DMODEL];
__device__ __half g_wo_h  [DMODEL * DMODEL];
__device__ __half g_fc1_h [FFDIM * DMODEL];
__device__ __half g_fc2_h [DMODEL * FFDIM];

// ---------------- helpers ----------------
__device__ __forceinline__ float warpSum(float v) {
    #pragma unroll
    for (int o = 16; o > 0; o >>= 1) v += __shfl_xor_sync(0xffffffffu, v, o);
    return v;
}
__device__ __forceinline__ void mma_f16(float* d, const uint32_t* a, const uint32_t* b) {
    asm volatile(
        "mma.sync.aligned.m16n8k16.row.col.f32.f16.f16.f32 "
        "{%0,%1,%2,%3}, {%4,%5,%6,%7}, {%8,%9}, {%0,%1,%2,%3};"
        : "+f"(d[0]), "+f"(d[1]), "+f"(d[2]), "+f"(d[3])
        : "r"(a[0]), "r"(a[1]), "r"(a[2]), "r"(a[3]), "r"(b[0]), "r"(b[1]));
}
__device__ __forceinline__ uint32_t smem_u32(const void* p) {
    return (uint32_t)__cvta_generic_to_shared(p);
}
__device__ __forceinline__ void ldsm_x4(uint32_t& r0, uint32_t& r1, uint32_t& r2,
                                        uint32_t& r3, uint32_t addr) {
    asm volatile("ldmatrix.sync.aligned.m8n8.x4.shared.b16 {%0,%1,%2,%3}, [%4];"
                 : "=r"(r0), "=r"(r1), "=r"(r2), "=r"(r3) : "r"(addr));
}
__device__ __forceinline__ void ldsm_x4_t(uint32_t& r0, uint32_t& r1, uint32_t& r2,
                                          uint32_t& r3, uint32_t addr) {
    asm volatile("ldmatrix.sync.aligned.m8n8.x4.trans.shared.b16 {%0,%1,%2,%3}, [%4];"
                 : "=r"(r0), "=r"(r1), "=r"(r2), "=r"(r3) : "r"(addr));
}
__device__ __forceinline__ uint32_t packh2(float a, float b) {
    __half2 h = __floats2half2_rn(a, b);
    return *(uint32_t*)&h;
}

// ---------------- weight conversion: fp32 -> fp16 ----------------
__global__ void cvt_half_kernel(const float4* __restrict__ in, uint2* __restrict__ out, int n4)
{
    int i = blockIdx.x * blockDim.x + threadIdx.x;
    if (i < n4) {
        float4 v = in[i];
        uint2 o;
        o.x = packh2(v.x, v.y);
        o.y = packh2(v.z, v.w);
        out[i] = o;
    }
}

// ---------------- LayerNorm -> half out ----------------
__global__ void ln_kernel(const float* __restrict__ x,
                          const float* __restrict__ w,
                          const float* __restrict__ b,
                          __half* __restrict__ y)
{
    int row = blockIdx.x;
    int tid = threadIdx.x;
    const float* xr = x + (size_t)row * DMODEL;
    float4 v = *(const float4*)&xr[tid * 4];

    float s  = v.x + v.y + v.z + v.w;
    float s2 = v.x * v.x + v.y * v.y + v.z * v.z + v.w * v.w;

    __shared__ float redS[8], redS2[8];
    int lane = tid & 31, wid = tid >> 5;
    s  = warpSum(s);
    s2 = warpSum(s2);
    if (lane == 0) { redS[wid] = s; redS2[wid] = s2; }
    __syncthreads();
    float ts = 0.f, ts2 = 0.f;
    #pragma unroll
    for (int i = 0; i < 8; i++) { ts += redS[i]; ts2 += redS2[i]; }
    float mean = ts * (1.0f / DMODEL);
    float var  = ts2 * (1.0f / DMODEL) - mean * mean;
    float r    = rsqrtf(var + 1e-5f);

    float4 wv = *(const float4*)&w[tid * 4];
    float4 bv = *(const float4*)&b[tid * 4];
    float o0 = (v.x - mean) * r * wv.x + bv.x;
    float o1 = (v.y - mean) * r * wv.y + bv.y;
    float o2 = (v.z - mean) * r * wv.z + bv.z;
    float o3 = (v.w - mean) * r * wv.w + bv.w;
    uint2 st;
    st.x = packh2(o0, o1);
    st.y = packh2(o2, o3);
    *(uint2*)&y[(size_t)row * DMODEL + tid * 4] = st;
}

// ---------------- fp16 tensor-core NT GEMM (512 threads, 128x256) ----------------
// C[M,N] = epilogue(A[M,K] @ B[N,K]^T + bias)
// MODE 0: (acc+bias)*alpha -> half   MODE 1: quick-gelu -> half   MODE 2: +res -> float
#define GBM 128
#define GBN 256
#define GBK 32      // halves per K-tile
#define PH  40      // smem pitch in halves (80B)
#define STG 4
#define GTHREADS 512

template<int MODE>
__device__ __forceinline__ void gemm_body(
    const __half* __restrict__ A, const __half* __restrict__ B,
    const float* __restrict__ bias, const float* __restrict__ res,
    void* __restrict__ Cv, int M, int N, int K, float alpha, int bm, int bn)
{
    __shared__ __half As[STG][GBM][PH];
    __shared__ __half Bs[STG][GBN][PH];

    const int tid  = threadIdx.x;
    const int lane = tid & 31;
    const int wid  = tid >> 5;          // 0..15
    const int wm   = (wid & 3) * 32;    // 4 warps over M (32 rows each)
    const int wn   = (wid >> 2) * 64;   // 4 warps over N (64 cols each)

    float acc[2][8][4];
    #pragma unroll
    for (int i = 0; i < 2; i++)
        #pragma unroll
        for (int j = 0; j < 8; j++)
            #pragma unroll
            for (int q = 0; q < 4; q++) acc[i][j][q] = 0.f;

    const int ktiles = K / GBK;

    auto load_tile = [&](int kt, int s) {
        // A: 128 rows x 4 chunks of 16B = 512 -> 1 per thread
        {
            int row = tid >> 2, ch = tid & 3;
            uint32_t dst = smem_u32(&As[s][row][ch * 8]);
            const __half* src = A + (size_t)(bm + row) * K + kt * GBK + ch * 8;
            int sz = (bm + row < M) ? 16 : 0;
            asm volatile("cp.async.ca.shared.global [%0], [%1], 16, %2;"
                         :: "r"(dst), "l"(src), "r"(sz));
        }
        // B: 256 rows x 4 chunks = 1024 -> 2 per thread
        #pragma unroll
        for (int i = 0; i < 2; i++) {
            int idx = tid + GTHREADS * i;
            int row = idx >> 2, ch = idx & 3;
            uint32_t dst = smem_u32(&Bs[s][row][ch * 8]);
            const __half* src = B + (size_t)(bn + row) * K + kt * GBK + ch * 8;
            asm volatile("cp.async.ca.shared.global [%0], [%1], 16;"
                         :: "r"(dst), "l"(src));
        }
        asm volatile("cp.async.commit_group;");
    };

    const int l15 = lane & 15;
    const int lhi = lane >> 4;

    auto compute_tile = [&](int s) {
        #pragma unroll
        for (int ks = 0; ks < 2; ks++) {
            const int kc = ks * 16 + lhi * 8;
            uint32_t af[2][4];
            uint32_t bf[8][2];
            #pragma unroll
            for (int mt = 0; mt < 2; mt++) {
                uint32_t adr = smem_u32(&As[s][wm + mt * 16 + l15][kc]);
                ldsm_x4(af[mt][0], af[mt][1], af[mt][2], af[mt][3], adr);
            }
            #pragma unroll
            for (int g = 0; g < 4; g++) {
                uint32_t adr = smem_u32(&Bs[s][wn + g * 16 + l15][kc]);
                ldsm_x4(bf[2*g][0], bf[2*g+1][0], bf[2*g][1], bf[2*g+1][1], adr);
            }
            #pragma unroll
            for (int mt = 0; mt < 2; mt++)
                #pragma unroll
                for (int nt = 0; nt < 8; nt++)
                    mma_f16(acc[mt][nt], af[mt], bf[nt]);
        }
    };

    #pragma unroll
    for (int s = 0; s < STG - 1; s++)
        if (s < ktiles) load_tile(s, s);

    int cur = 0, pre = STG - 1;
    for (int kt = 0; kt < ktiles; kt++) {
        asm volatile("cp.async.wait_group %0;" :: "n"(STG - 2));
        __syncthreads();
        if (kt + STG - 1 < ktiles) load_tile(kt + STG - 1, pre);
        compute_tile(cur);
        cur = (cur + 1 == STG) ? 0 : cur + 1;
        pre = (pre + 1 == STG) ? 0 : pre + 1;
    }

    // epilogue
    #pragma unroll
    for (int mt = 0; mt < 2; mt++) {
        int row0 = bm + wm + mt * 16 + (lane >> 2);
        #pragma unroll
        for (int nt = 0; nt < 8; nt++) {
            int col = bn + wn + nt * 8 + (lane & 3) * 2;
            float b0 = bias[col], b1 = bias[col + 1];
            #pragma unroll
            for (int h = 0; h < 2; h++) {
                int row = row0 + h * 8;
                if (row >= M) continue;
                float v0 = acc[mt][nt][h * 2 + 0] + b0;
                float v1 = acc[mt][nt][h * 2 + 1] + b1;
                if (MODE == 0) {
                    v0 *= alpha; v1 *= alpha;
                    *(uint32_t*)&((__half*)Cv)[(size_t)row * N + col] = packh2(v0, v1);
                } else if (MODE == 1) {
                    v0 = v0 / (1.0f + expf(-1.702f * v0));
                    v1 = v1 / (1.0f + expf(-1.702f * v1));
                    *(uint32_t*)&((__half*)Cv)[(size_t)row * N + col] = packh2(v0, v1);
                } else {
                    const float* rr = &res[(size_t)row * N + col];
                    v0 += rr[0]; v1 += rr[1];
                    *(float2*)&((float*)Cv)[(size_t)row * N + col] = make_float2(v0, v1);
                }
            }
        }
    }
}

template<int MODE>
__global__ __launch_bounds__(GTHREADS, 1)
void gemm_h(const __half* __restrict__ A, const __half* __restrict__ B,
            const float* __restrict__ bias, const float* __restrict__ res,
            void* __restrict__ C, int M, int N, int K, float alpha)
{
    gemm_body<MODE>(A, B, bias, res, C, M, N, K, alpha,
                    blockIdx.y * GBM, blockIdx.x * GBN);
}

__global__ __launch_bounds__(GTHREADS, 1)
void gemm_qkv(const __half* __restrict__ A,
              const __half* __restrict__ wq, const __half* __restrict__ wk,
              const __half* __restrict__ wv,
              const float* __restrict__ bq, const float* __restrict__ bk,
              const float* __restrict__ bv,
              __half* __restrict__ q, __half* __restrict__ k, __half* __restrict__ v,
              int M, int K)
{
    const int which = blockIdx.x >> 2;
    const int bn = (blockIdx.x & 3) * GBN;
    const __half* B   = (which == 0) ? wq : (which == 1) ? wk : wv;
    const float* bias = (which == 0) ? bq : (which == 1) ? bk : bv;
    __half* C         = (which == 0) ? q  : (which == 1) ? k  : v;
    const float alpha = (which == 0) ? QK_SCALE : 1.0f;
    gemm_body<0>(A, B, bias, nullptr, C, M, DMODEL, K, alpha,
                 blockIdx.y * GBM, bn);
}

// ---------------- flash attention (fp16 mma, online softmax) ----------------
// qtile=128, 8 warps; warp w owns q rows w*16..w*16+15 across full width.
#define FQT 128
#define FKT 64
#define FNT 5           // ceil(257/64)
#define FPH 72          // smem pitch in halves (144B)

__global__ __launch_bounds__(256)
void fattn(const __half* __restrict__ Q, const __half* __restrict__ K,
           const __half* __restrict__ V, __half* __restrict__ O)
{
    __shared__ __half Qs[FQT][FPH];
    __shared__ __half Ks[FKT][FPH];
    __shared__ __half Vs[FKT][FPH];

    const int qt  = blockIdx.x * FQT;
    const int bh  = blockIdx.y;
    const int b   = bh >> 4, h = bh & 15;
    const size_t base = (size_t)b * NSEQ * DMODEL + (size_t)h * HDIM;
    const int tid  = threadIdx.x;
    const int lane = tid & 31;
    const int wid  = tid >> 5;
    const int qr0  = wid * 16;
    const int l15  = lane & 15;
    const int lhi  = lane >> 4;

    // load Q tile [128 q][64 d]: 128*8 chunks / 256 thr = 4 each
    #pragma unroll
    for (int i = 0; i < 4; i++) {
        int idx = tid + 256 * i;
        int row = idx >> 3, ch = idx & 7;
        uint4 v = make_uint4(0u, 0u, 0u, 0u);
        if (qt + row < NSEQ)
            v = *(const uint4*)&Q[base + (size_t)(qt + row) * DMODEL + ch * 8];
        *(uint4*)&Qs[row][ch * 8] = v;
    }
    __syncthreads();

    // preload Q fragments (K=64 -> 4 k-steps)
    uint32_t afq[4][4];
    #pragma unroll
    for (int ks = 0; ks < 4; ks++)
        ldsm_x4(afq[ks][0], afq[ks][1], afq[ks][2], afq[ks][3],
                smem_u32(&Qs[qr0 + l15][ks * 16 + lhi * 8]));

    float m0 = -1e30f, m1 = -1e30f, l0 = 0.f, l1 = 0.f;
    float accO[8][4];
    #pragma unroll
    for (int nt = 0; nt < 8; nt++)
        #pragma unroll
        for (int q = 0; q < 4; q++) accO[nt][q] = 0.f;

    for (int t = 0; t < FNT; t++) {
        const int kt0 = t * FKT;
        __syncthreads();
        // load K and V tiles: 64*8 chunks each = 512 -> 2 per thread each
        #pragma unroll
        for (int i = 0; i < 2; i++) {
            int idx = tid + 256 * i;
            int row = idx >> 3, ch = idx & 7;
            uint4 kv = make_uint4(0u, 0u, 0u, 0u);
            uint4 vv = make_uint4(0u, 0u, 0u, 0u);
            if (kt0 + row < NSEQ) {
                kv = *(const uint4*)&K[base + (size_t)(kt0 + row) * DMODEL + ch * 8];
                vv = *(const uint4*)&V[base + (size_t)(kt0 + row) * DMODEL + ch * 8];
            }
            *(uint4*)&Ks[row][ch * 8] = kv;
            *(uint4*)&Vs[row][ch * 8] = vv;
        }
        __syncthreads();

        // ---- S = Q K^T (16 x 64) ----
        float accS[8][4];
        #pragma unroll
        for (int nt = 0; nt < 8; nt++)
            #pragma unroll
            for (int q = 0; q < 4; q++) accS[nt][q] = 0.f;

        #pragma unroll
        for (int ks = 0; ks < 4; ks++) {
            const int kc = ks * 16 + lhi * 8;
            uint32_t bf[8][2];
            #pragma unroll
            for (int g = 0; g < 4; g++)
                ldsm_x4(bf[2*g][0], bf[2*g+1][0], bf[2*g][1], bf[2*g+1][1],
                        smem_u32(&Ks[g * 16 + l15][kc]));
            #pragma unroll
            for (int nt = 0; nt < 8; nt++)
                mma_f16(accS[nt], afq[ks], bf[nt]);
        }

        // ---- mask + row max (rows r and r+8; 4 threads per row) ----
        const int cbase = kt0 + (lane & 3) * 2;
        float tm0 = -1e30f, tm1 = -1e30f;
        #pragma unroll
        for (int nt = 0; nt < 8; nt++) {
            int c0 = cbase + nt * 8;
            if (c0 >= NSEQ)     { accS[nt][0] = -1e30f; accS[nt][2] = -1e30f; }
            if (c0 + 1 >= NSEQ) { accS[nt][1] = -1e30f; accS[nt][3] = -1e30f; }
            tm0 = fmaxf(tm0, fmaxf(accS[nt][0], accS[nt][1]));
            tm1 = fmaxf(tm1, fmaxf(accS[nt][2], accS[nt][3]));
        }
        tm0 = fmaxf(tm0, __shfl_xor_sync(0xffffffffu, tm0, 1));
        tm0 = fmaxf(tm0, __shfl_xor_sync(0xffffffffu, tm0, 2));
        tm1 = fmaxf(tm1, __shfl_xor_sync(0xffffffffu, tm1, 1));
        tm1 = fmaxf(tm1, __shfl_xor_sync(0xffffffffu, tm1, 2));

        float mn0 = fmaxf(m0, tm0), mn1 = fmaxf(m1, tm1);
        float sc0 = __expf(m0 - mn0), sc1 = __expf(m1 - mn1);
        m0 = mn0; m1 = mn1;

        // ---- P = exp(S - m); pack A-fragments for PV directly from regs ----
        uint32_t pf[4][4];
        float s0 = 0.f, s1 = 0.f;
        #pragma unroll
        for (int j = 0; j < 4; j++) {
            #pragma unroll
            for (int e = 0; e < 2; e++) {
                int nt = 2 * j + e;
                float p0 = __expf(accS[nt][0] - m0);
                float p1 = __expf(accS[nt][1] - m0);
                float p2 = __expf(accS[nt][2] - m1);
                float p3 = __expf(accS[nt][3] - m1);
                s0 += p0 + p1; s1 += p2 + p3;
                pf[j][0 + 2*e] = packh2(p0, p1);
                pf[j][1 + 2*e] = packh2(p2, p3);
            }
        }
        s0 += __shfl_xor_sync(0xffffffffu, s0, 1);
        s0 += __shfl_xor_sync(0xffffffffu, s0, 2);
        s1 += __shfl_xor_sync(0xffffffffu, s1, 1);
        s1 += __shfl_xor_sync(0xffffffffu, s1, 2);
        l0 = l0 * sc0 + s0;
        l1 = l1 * sc1 + s1;

        #pragma unroll
        for (int nt = 0; nt < 8; nt++) {
            accO[nt][0] *= sc0; accO[nt][1] *= sc0;
            accO[nt][2] *= sc1; accO[nt][3] *= sc1;
        }

        // ---- O += P V ----
        #pragma unroll
        for (int j = 0; j < 4; j++) {
            uint32_t bv[8][2];
            #pragma unroll
            for (int g = 0; g < 4; g++)
                ldsm_x4_t(bv[2*g][0], bv[2*g][1], bv[2*g+1][0], bv[2*g+1][1],
                          smem_u32(&Vs[j * 16 + l15][g * 16 + lhi * 8]));
            #pragma unroll
            for (int nt = 0; nt < 8; nt++)
                mma_f16(accO[nt], pf[j], bv[nt]);
        }
    }

    // ---- epilogue: O / l ----
    {
        int r = lane >> 2;
        int row0 = qt + qr0 + r;
        int row1 = row0 + 8;
        float i0 = 1.0f / l0, i1 = 1.0f / l1;
        #pragma unroll
        for (int nt = 0; nt < 8; nt++) {
            int col = nt * 8 + (lane & 3) * 2;
            if (row0 < NSEQ)
                *(uint32_t*)&O[base + (size_t)row0 * DMODEL + col] =
                    packh2(accO[nt][0] * i0, accO[nt][1] * i0);
            if (row1 < NSEQ)
                *(uint32_t*)&O[base + (size_t)row1 * DMODEL + col] =
                    packh2(accO[nt][2] * i1, accO[nt][3] * i1);
        }
    }
}

// ---------------- launch ----------------
extern "C" void kernel_launch(void* const* d_in, const int* in_sizes, int n_in,
                              void* d_out, int out_size)
{
    const float* hs     = (const float*)d_in[0];
    const float* ln1_w  = (const float*)d_in[1];
    const float* ln1_b  = (const float*)d_in[2];
    const float* wq     = (const float*)d_in[3];
    const float* bq     = (const float*)d_in[4];
    const float* wk     = (const float*)d_in[5];
    const float* bk     = (const float*)d_in[6];
    const float* wv     = (const float*)d_in[7];
    const float* bv     = (const float*)d_in[8];
    const float* wo     = (const float*)d_in[9];
    const float* bo     = (const float*)d_in[10];
    const float* ln2_w  = (const float*)d_in[11];
    const float* ln2_b  = (const float*)d_in[12];
    const float* fc1_w  = (const float*)d_in[13];
    const float* fc1_b  = (const float*)d_in[14];
    const float* fc2_w  = (const float*)d_in[15];
    const float* fc2_b  = (const float*)d_in[16];
    float* out          = (float*)d_out;

    static __half *xln=nullptr,*q=nullptr,*k=nullptr,*v=nullptr,*attn=nullptr,
                  *h2=nullptr,*ff=nullptr,
                  *wqh=nullptr,*wkh=nullptr,*wvh=nullptr,*woh=nullptr,
                  *fc1h=nullptr,*fc2h=nullptr;
    static float *hidden=nullptr;
    if (!xln) {
        cudaGetSymbolAddress((void**)&xln,    g_xln_h);
        cudaGetSymbolAddress((void**)&q,      g_q_h);
        cudaGetSymbolAddress((void**)&k,      g_k_h);
        cudaGetSymbolAddress((void**)&v,      g_v_h);
        cudaGetSymbolAddress((void**)&attn,   g_attn_h);
        cudaGetSymbolAddress((void**)&hidden, g_hidden);
        cudaGetSymbolAddress((void**)&h2,     g_h2_h);
        cudaGetSymbolAddress((void**)&ff,     g_ff_h);
        cudaGetSymbolAddress((void**)&wqh,    g_wq_h);
        cudaGetSymbolAddress((void**)&wkh,    g_wk_h);
        cudaGetSymbolAddress((void**)&wvh,    g_wv_h);
        cudaGetSymbolAddress((void**)&woh,    g_wo_h);
        cudaGetSymbolAddress((void**)&fc1h,   g_fc1_h);
        cudaGetSymbolAddress((void**)&fc2h,   g_fc2_h);
    }

    const int mtiles = (TOK + GBM - 1) / GBM;   // 81
    const int n4w = DMODEL * DMODEL / 4;
    const int n4f = FFDIM * DMODEL / 4;

    // 0) convert weights to half
    cvt_half_kernel<<<n4w / 256, 256>>>((const float4*)wq,    (uint2*)wqh,  n4w);
    cvt_half_kernel<<<n4w / 256, 256>>>((const float4*)wk,    (uint2*)wkh,  n4w);
    cvt_half_kernel<<<n4w / 256, 256>>>((const float4*)wv,    (uint2*)wvh,  n4w);
    cvt_half_kernel<<<n4w / 256, 256>>>((const float4*)wo,    (uint2*)woh,  n4w);
    cvt_half_kernel<<<n4f / 256, 256>>>((const float4*)fc1_w, (uint2*)fc1h, n4f);
    cvt_half_kernel<<<n4f / 256, 256>>>((const float4*)fc2_w, (uint2*)fc2h, n4f);

    // 1) LN1 -> half
    ln_kernel<<<TOK, 256>>>(hs, ln1_w, ln1_b, xln);

    // 2) fused QKV projections
    gemm_qkv<<<dim3(12, mtiles), GTHREADS>>>(xln, wqh, wkh, wvh, bq, bk, bv,
                                             q, k, v, TOK, DMODEL);

    // 3) flash attention
    fattn<<<dim3((NSEQ + FQT - 1) / FQT, BATCH * NHEAD), 256>>>(q, k, v, attn);

    // 4) O projection + residual -> fp32 hidden
    gemm_h<2><<<dim3(DMODEL/GBN, mtiles), GTHREADS>>>(attn, woh, bo, hs, hidden,
                                                      TOK, DMODEL, DMODEL, 1.0f);

    // 5) LN2 -> half
    ln_kernel<<<TOK, 256>>>(hidden, ln2_w, ln2_b, h2);

    // 6) FC1 + quick-gelu -> half
    gemm_h<1><<<dim3(FFDIM/GBN, mtiles), GTHREADS>>>(h2, fc1h, fc1_b, nullptr, ff,
                                                     TOK, FFDIM, DMODEL, 1.0f);

    // 7) FC2 + residual -> fp32 output
    gemm_h<2><<<dim3(DMODEL/GBN, mtiles), GTHREADS>>>(ff, fc2h, fc2_b, hidden, out,
                                                      TOK, DMODEL, FFDIM, 1.0f);
}